// round 2
// baseline (speedup 1.0000x reference)
#include <cuda_runtime.h>
#include <math.h>

#define NTOK 4096
#define DMODEL 1024
#define DFF 512
#define NH 16
#define DH 64
#define SEQ 2048

// Scratch (device globals: allocation-free, graph-capture safe)
__device__ float g_xn[NTOK * DMODEL];
__device__ float g_q[NTOK * DMODEL];
__device__ float g_k[NTOK * DMODEL];
__device__ float g_v[NTOK * DMODEL];
__device__ float g_attn[NTOK * DMODEL];
__device__ float g_x1[NTOK * DMODEL];
__device__ float g_h[NTOK * DMODEL];
__device__ float g_hf[NTOK * DFF];

// ---------------------------------------------------------------------------
// LayerNorm with UNBIASED variance (N-1), matching reference
// one block (256 threads) per row of 1024
// ---------------------------------------------------------------------------
__global__ void ln_kernel(const float* __restrict__ x,
                          const float* __restrict__ alpha,
                          const float* __restrict__ beta,
                          float* __restrict__ y) {
    int row = blockIdx.x;
    int t = threadIdx.x;
    const float4* xr = (const float4*)(x + (size_t)row * DMODEL);
    float4 v = xr[t];
    float s  = v.x + v.y + v.z + v.w;
    float ss = v.x * v.x + v.y * v.y + v.z * v.z + v.w * v.w;
    __shared__ float sbuf[8], sbuf2[8];
#pragma unroll
    for (int m = 16; m; m >>= 1) {
        s  += __shfl_xor_sync(0xffffffffu, s, m);
        ss += __shfl_xor_sync(0xffffffffu, ss, m);
    }
    if ((t & 31) == 0) { sbuf[t >> 5] = s; sbuf2[t >> 5] = ss; }
    __syncthreads();
    if (t < 32) {
        s  = (t < 8) ? sbuf[t]  : 0.0f;
        ss = (t < 8) ? sbuf2[t] : 0.0f;
#pragma unroll
        for (int m = 4; m; m >>= 1) {
            s  += __shfl_xor_sync(0xffffffffu, s, m);
            ss += __shfl_xor_sync(0xffffffffu, ss, m);
        }
        if (t == 0) { sbuf[0] = s; sbuf2[0] = ss; }
    }
    __syncthreads();
    s = sbuf[0]; ss = sbuf2[0];
    float mean = s * (1.0f / DMODEL);
    float var  = (ss - (float)DMODEL * mean * mean) * (1.0f / (DMODEL - 1));
    float rstd = rsqrtf(var + 1e-6f);
    float4 a = ((const float4*)alpha)[t];
    float4 b = ((const float4*)beta)[t];
    float4 o;
    o.x = a.x * (v.x - mean) * rstd + b.x;
    o.y = a.y * (v.y - mean) * rstd + b.y;
    o.z = a.z * (v.z - mean) * rstd + b.z;
    o.w = a.w * (v.w - mean) * rstd + b.w;
    ((float4*)(y + (size_t)row * DMODEL))[t] = o;
}

// ---------------------------------------------------------------------------
// Tiled SIMT GEMM: C[M,N] = A[M,K] @ B[K,N] + bias (+ residual) (+ relu)
// BM=BN=128, BK=8, 256 threads, 8x8 microtile per thread
// ---------------------------------------------------------------------------
__global__ void gemm_kernel(const float* __restrict__ A, const float* __restrict__ Bm,
                            const float* __restrict__ bias, const float* __restrict__ res,
                            float* __restrict__ C, int M, int N, int K, int relu) {
    __shared__ float As[8 * 128];
    __shared__ float Bs[8 * 128];
    int t = threadIdx.x;
    int bm = blockIdx.y, bn = blockIdx.x;
    int arow = t >> 1, ac4 = (t & 1) * 4;
    int brow = t >> 5, bc4 = (t & 31) * 4;
    const float* Ap = A + ((size_t)(bm * 128 + arow)) * K + ac4;
    const float* Bp = Bm + (size_t)brow * N + bn * 128 + bc4;
    int ty = t >> 4, tx = t & 15;
    float acc[8][8];
#pragma unroll
    for (int i = 0; i < 8; i++)
#pragma unroll
        for (int j = 0; j < 8; j++) acc[i][j] = 0.0f;

    for (int k0 = 0; k0 < K; k0 += 8) {
        float4 av = *(const float4*)(Ap + k0);
        float4 bv = *(const float4*)(Bp + (size_t)k0 * N);
        As[(ac4 + 0) * 128 + arow] = av.x;
        As[(ac4 + 1) * 128 + arow] = av.y;
        As[(ac4 + 2) * 128 + arow] = av.z;
        As[(ac4 + 3) * 128 + arow] = av.w;
        *(float4*)(Bs + brow * 128 + bc4) = bv;
        __syncthreads();
#pragma unroll
        for (int k = 0; k < 8; k++) {
            float a[8], b[8];
            *(float4*)(a)     = *(const float4*)(As + k * 128 + ty * 8);
            *(float4*)(a + 4) = *(const float4*)(As + k * 128 + ty * 8 + 4);
            *(float4*)(b)     = *(const float4*)(Bs + k * 128 + tx * 8);
            *(float4*)(b + 4) = *(const float4*)(Bs + k * 128 + tx * 8 + 4);
#pragma unroll
            for (int i = 0; i < 8; i++)
#pragma unroll
                for (int j = 0; j < 8; j++) acc[i][j] = fmaf(a[i], b[j], acc[i][j]);
        }
        __syncthreads();
    }

    int crow0 = bm * 128 + ty * 8;
    int ccol0 = bn * 128 + tx * 8;
#pragma unroll
    for (int i = 0; i < 8; i++) {
        size_t r = crow0 + i;
#pragma unroll
        for (int jj = 0; jj < 8; jj += 4) {
            float4 bb = *(const float4*)(bias + ccol0 + jj);
            float4 o;
            o.x = acc[i][jj + 0] + bb.x;
            o.y = acc[i][jj + 1] + bb.y;
            o.z = acc[i][jj + 2] + bb.z;
            o.w = acc[i][jj + 3] + bb.w;
            if (res) {
                float4 rr = *(const float4*)(res + r * N + ccol0 + jj);
                o.x += rr.x; o.y += rr.y; o.z += rr.z; o.w += rr.w;
            }
            if (relu) {
                o.x = fmaxf(o.x, 0.0f); o.y = fmaxf(o.y, 0.0f);
                o.z = fmaxf(o.z, 0.0f); o.w = fmaxf(o.w, 0.0f);
            }
            *(float4*)(C + r * N + ccol0 + jj) = o;
        }
    }
}

// ---------------------------------------------------------------------------
// Flash attention (fp32, online softmax). Block = 256 threads handles
// one (batch, head, 64-row q-tile). Streams over 32 key tiles of 64.
// K stored transposed in smem; P overwrites K's smem after S is computed.
// ---------------------------------------------------------------------------
__global__ void attn_kernel(const float* __restrict__ q, const float* __restrict__ k,
                            const float* __restrict__ v, float* __restrict__ o) {
    __shared__ float Qs[64 * 64];
    __shared__ float KP[64 * 64];   // holds K^T, then P
    __shared__ float Vs[64 * 64];
    int tid = threadIdx.x;
    int qt = blockIdx.x, h = blockIdx.y, b = blockIdx.z;
    int col0 = h * DH;
    const float* qb = q + ((size_t)(b * SEQ + qt * 64)) * DMODEL + col0;

    // load Q tile pre-scaled by 1/sqrt(dh)
#pragma unroll
    for (int it = 0; it < 4; it++) {
        int idx = it * 256 + tid;
        int r = idx >> 4, c4 = (idx & 15) * 4;
        float4 qv = *(const float4*)(qb + (size_t)r * DMODEL + c4);
        qv.x *= 0.125f; qv.y *= 0.125f; qv.z *= 0.125f; qv.w *= 0.125f;
        *(float4*)(Qs + r * 64 + c4) = qv;
    }

    int ty = tid >> 4, tx = tid & 15;
    float mrow[4], lrow[4], Oacc[4][4];
#pragma unroll
    for (int i = 0; i < 4; i++) {
        mrow[i] = -1e30f; lrow[i] = 0.0f;
#pragma unroll
        for (int j = 0; j < 4; j++) Oacc[i][j] = 0.0f;
    }

    for (int kt = 0; kt < 32; kt++) {
        const float* kb = k + ((size_t)(b * SEQ + kt * 64)) * DMODEL + col0;
        const float* vb = v + ((size_t)(b * SEQ + kt * 64)) * DMODEL + col0;
        __syncthreads();   // previous iteration done reading KP/Vs (also covers Q-load on kt=0)
#pragma unroll
        for (int it = 0; it < 4; it++) {
            int idx = it * 256 + tid;
            int r = idx >> 4, c4 = (idx & 15) * 4;
            float4 kv = *(const float4*)(kb + (size_t)r * DMODEL + c4);
            KP[(c4 + 0) * 64 + r] = kv.x;
            KP[(c4 + 1) * 64 + r] = kv.y;
            KP[(c4 + 2) * 64 + r] = kv.z;
            KP[(c4 + 3) * 64 + r] = kv.w;
            float4 vv = *(const float4*)(vb + (size_t)r * DMODEL + c4);
            *(float4*)(Vs + r * 64 + c4) = vv;
        }
        __syncthreads();

        // S tile: Sv[i][j] = sum_d Q[qrow][d] * Kt[d][kcol]
        float Sv[4][4];
#pragma unroll
        for (int i = 0; i < 4; i++)
#pragma unroll
            for (int j = 0; j < 4; j++) Sv[i][j] = 0.0f;
        for (int d = 0; d < 64; d += 4) {
            float4 qv[4], kv[4];
#pragma unroll
            for (int i = 0; i < 4; i++) qv[i] = *(const float4*)(Qs + (ty * 4 + i) * 64 + d);
#pragma unroll
            for (int j = 0; j < 4; j++) kv[j] = *(const float4*)(KP + (d + j) * 64 + tx * 4);
#pragma unroll
            for (int i = 0; i < 4; i++) {
                Sv[i][0] = fmaf(qv[i].x, kv[0].x, Sv[i][0]);
                Sv[i][1] = fmaf(qv[i].x, kv[0].y, Sv[i][1]);
                Sv[i][2] = fmaf(qv[i].x, kv[0].z, Sv[i][2]);
                Sv[i][3] = fmaf(qv[i].x, kv[0].w, Sv[i][3]);
                Sv[i][0] = fmaf(qv[i].y, kv[1].x, Sv[i][0]);
                Sv[i][1] = fmaf(qv[i].y, kv[1].y, Sv[i][1]);
                Sv[i][2] = fmaf(qv[i].y, kv[1].z, Sv[i][2]);
                Sv[i][3] = fmaf(qv[i].y, kv[1].w, Sv[i][3]);
                Sv[i][0] = fmaf(qv[i].z, kv[2].x, Sv[i][0]);
                Sv[i][1] = fmaf(qv[i].z, kv[2].y, Sv[i][1]);
                Sv[i][2] = fmaf(qv[i].z, kv[2].z, Sv[i][2]);
                Sv[i][3] = fmaf(qv[i].z, kv[2].w, Sv[i][3]);
                Sv[i][0] = fmaf(qv[i].w, kv[3].x, Sv[i][0]);
                Sv[i][1] = fmaf(qv[i].w, kv[3].y, Sv[i][1]);
                Sv[i][2] = fmaf(qv[i].w, kv[3].z, Sv[i][2]);
                Sv[i][3] = fmaf(qv[i].w, kv[3].w, Sv[i][3]);
            }
        }

        __syncthreads();   // everyone done reading KP as K^T

        // online softmax update (registers + 16-lane shuffles)
#pragma unroll
        for (int i = 0; i < 4; i++) {
            float rm = fmaxf(fmaxf(Sv[i][0], Sv[i][1]), fmaxf(Sv[i][2], Sv[i][3]));
#pragma unroll
            for (int m = 1; m < 16; m <<= 1) rm = fmaxf(rm, __shfl_xor_sync(0xffffffffu, rm, m));
            float mnew = fmaxf(mrow[i], rm);
            float alpha = __expf(mrow[i] - mnew);
            mrow[i] = mnew;
            float rs = 0.0f;
#pragma unroll
            for (int j = 0; j < 4; j++) {
                Sv[i][j] = __expf(Sv[i][j] - mnew);
                rs += Sv[i][j];
            }
#pragma unroll
            for (int m = 1; m < 16; m <<= 1) rs += __shfl_xor_sync(0xffffffffu, rs, m);
            lrow[i] = lrow[i] * alpha + rs;
#pragma unroll
            for (int j = 0; j < 4; j++) Oacc[i][j] *= alpha;
        }

        // write P over K's smem
#pragma unroll
        for (int i = 0; i < 4; i++)
            *(float4*)(KP + (ty * 4 + i) * 64 + tx * 4) = *(float4*)(&Sv[i][0]);
        __syncthreads();

        // O += P @ V
        for (int kk = 0; kk < 64; kk += 4) {
            float4 pv[4], vv[4];
#pragma unroll
            for (int i = 0; i < 4; i++) pv[i] = *(const float4*)(KP + (ty * 4 + i) * 64 + kk);
#pragma unroll
            for (int j = 0; j < 4; j++) vv[j] = *(const float4*)(Vs + (kk + j) * 64 + tx * 4);
#pragma unroll
            for (int i = 0; i < 4; i++) {
                Oacc[i][0] = fmaf(pv[i].x, vv[0].x, Oacc[i][0]);
                Oacc[i][1] = fmaf(pv[i].x, vv[0].y, Oacc[i][1]);
                Oacc[i][2] = fmaf(pv[i].x, vv[0].z, Oacc[i][2]);
                Oacc[i][3] = fmaf(pv[i].x, vv[0].w, Oacc[i][3]);
                Oacc[i][0] = fmaf(pv[i].y, vv[1].x, Oacc[i][0]);
                Oacc[i][1] = fmaf(pv[i].y, vv[1].y, Oacc[i][1]);
                Oacc[i][2] = fmaf(pv[i].y, vv[1].z, Oacc[i][2]);
                Oacc[i][3] = fmaf(pv[i].y, vv[1].w, Oacc[i][3]);
                Oacc[i][0] = fmaf(pv[i].z, vv[2].x, Oacc[i][0]);
                Oacc[i][1] = fmaf(pv[i].z, vv[2].y, Oacc[i][1]);
                Oacc[i][2] = fmaf(pv[i].z, vv[2].z, Oacc[i][2]);
                Oacc[i][3] = fmaf(pv[i].z, vv[2].w, Oacc[i][3]);
                Oacc[i][0] = fmaf(pv[i].w, vv[3].x, Oacc[i][0]);
                Oacc[i][1] = fmaf(pv[i].w, vv[3].y, Oacc[i][1]);
                Oacc[i][2] = fmaf(pv[i].w, vv[3].z, Oacc[i][2]);
                Oacc[i][3] = fmaf(pv[i].w, vv[3].w, Oacc[i][3]);
            }
        }
    }

    // finalize: divide by l and store
#pragma unroll
    for (int i = 0; i < 4; i++) {
        float inv = 1.0f / lrow[i];
        float4 ov;
        ov.x = Oacc[i][0] * inv;
        ov.y = Oacc[i][1] * inv;
        ov.z = Oacc[i][2] * inv;
        ov.w = Oacc[i][3] * inv;
        size_t row = (size_t)(b * SEQ + qt * 64 + ty * 4 + i);
        *(float4*)(o + row * DMODEL + col0 + tx * 4) = ov;
    }
}

// ---------------------------------------------------------------------------
extern "C" void kernel_launch(void* const* d_in, const int* in_sizes, int n_in,
                              void* d_out, int out_size) {
    const float* x      = (const float*)d_in[0];
    const float* Wq     = (const float*)d_in[1];
    const float* bq     = (const float*)d_in[2];
    const float* Wk     = (const float*)d_in[3];
    const float* bk     = (const float*)d_in[4];
    const float* Wv     = (const float*)d_in[5];
    const float* bv     = (const float*)d_in[6];
    const float* Wo     = (const float*)d_in[7];
    const float* bo     = (const float*)d_in[8];
    const float* alpha1 = (const float*)d_in[9];
    const float* beta1  = (const float*)d_in[10];
    const float* alpha2 = (const float*)d_in[11];
    const float* beta2  = (const float*)d_in[12];
    const float* W1     = (const float*)d_in[13];
    const float* b1     = (const float*)d_in[14];
    const float* W2     = (const float*)d_in[15];
    const float* b2     = (const float*)d_in[16];
    float* out = (float*)d_out;

    float *p_xn, *p_q, *p_k, *p_v, *p_attn, *p_x1, *p_h, *p_hf;
    cudaGetSymbolAddress((void**)&p_xn,   g_xn);
    cudaGetSymbolAddress((void**)&p_q,    g_q);
    cudaGetSymbolAddress((void**)&p_k,    g_k);
    cudaGetSymbolAddress((void**)&p_v,    g_v);
    cudaGetSymbolAddress((void**)&p_attn, g_attn);
    cudaGetSymbolAddress((void**)&p_x1,   g_x1);
    cudaGetSymbolAddress((void**)&p_h,    g_h);
    cudaGetSymbolAddress((void**)&p_hf,   g_hf);

    // 1. norm_1(x) -> xn (feeds attention AND the residual)
    ln_kernel<<<NTOK, 256>>>(x, alpha1, beta1, p_xn);

    // 2. Q, K, V projections
    dim3 gproj(DMODEL / 128, NTOK / 128);
    gemm_kernel<<<gproj, 256>>>(p_xn, Wq, bq, nullptr, p_q, NTOK, DMODEL, DMODEL, 0);
    gemm_kernel<<<gproj, 256>>>(p_xn, Wk, bk, nullptr, p_k, NTOK, DMODEL, DMODEL, 0);
    gemm_kernel<<<gproj, 256>>>(p_xn, Wv, bv, nullptr, p_v, NTOK, DMODEL, DMODEL, 0);

    // 3. attention
    dim3 gattn(SEQ / 64, NH, 2);
    attn_kernel<<<gattn, 256>>>(p_q, p_k, p_v, p_attn);

    // 4. O projection + residual(xn) -> x1
    gemm_kernel<<<gproj, 256>>>(p_attn, Wo, bo, p_xn, p_x1, NTOK, DMODEL, DMODEL, 0);

    // 5. norm_2(x1) -> h
    ln_kernel<<<NTOK, 256>>>(p_x1, alpha2, beta2, p_h);

    // 6. FF1 + relu -> hf
    dim3 gff1(DFF / 128, NTOK / 128);
    gemm_kernel<<<gff1, 256>>>(p_h, W1, b1, nullptr, p_hf, NTOK, DFF, DMODEL, 1);

    // 7. FF2 + residual(x1) -> out
    dim3 gff2(DMODEL / 128, NTOK / 128);
    gemm_kernel<<<gff2, 256>>>(p_hf, W2, b2, p_x1, out, NTOK, DMODEL, DFF, 0);
}

// round 3
// speedup vs baseline: 5.3606x; 5.3606x over previous
#include <cuda_runtime.h>
#include <cuda_fp16.h>
#include <math.h>

#define NTOK 4096
#define DMODEL 1024
#define DFF 512
#define NH 16
#define DH 64
#define SEQ 2048

// ---------------- scratch (device globals: alloc-free, capture-safe) -------
__device__ float  g_xn[NTOK * DMODEL];          // LN1 out fp32 (residual)
__device__ __half g_xn_h[NTOK * DMODEL];        // LN1 out half (GEMM A)
__device__ __half g_qkv[NTOK * 3 * DMODEL];     // fused QKV out half
__device__ __half g_attn_h[NTOK * DMODEL];      // attention out half
__device__ float  g_x1[NTOK * DMODEL];          // x + o_proj fp32
__device__ __half g_h_h[NTOK * DMODEL];         // LN2 out half
__device__ __half g_hf[NTOK * DFF];             // relu(ff1) half
__device__ __half g_Wqkv[3 * DMODEL * DMODEL];  // [3072][1024] n-major halves
__device__ __half g_WoT[DMODEL * DMODEL];
__device__ __half g_W1T[DFF * DMODEL];          // [512][1024]
__device__ __half g_W2T[DMODEL * DFF];          // [1024][512]
__device__ float  g_bqkv[3 * DMODEL];

// ---------------- PTX helpers ---------------------------------------------
__device__ __forceinline__ unsigned sptr(const void* p) {
    return (unsigned)__cvta_generic_to_shared(p);
}
__device__ __forceinline__ void ldsm4(unsigned* r, unsigned addr) {
    asm volatile("ldmatrix.sync.aligned.m8n8.x4.shared.b16 {%0,%1,%2,%3}, [%4];"
        : "=r"(r[0]), "=r"(r[1]), "=r"(r[2]), "=r"(r[3]) : "r"(addr));
}
__device__ __forceinline__ void ldsm4t(unsigned* r, unsigned addr) {
    asm volatile("ldmatrix.sync.aligned.m8n8.x4.trans.shared.b16 {%0,%1,%2,%3}, [%4];"
        : "=r"(r[0]), "=r"(r[1]), "=r"(r[2]), "=r"(r[3]) : "r"(addr));
}
__device__ __forceinline__ void mma16816(float* c, const unsigned* a, unsigned b0, unsigned b1) {
    asm volatile("mma.sync.aligned.m16n8k16.row.col.f32.f16.f16.f32 "
        "{%0,%1,%2,%3},{%4,%5,%6,%7},{%8,%9},{%0,%1,%2,%3};"
        : "+f"(c[0]), "+f"(c[1]), "+f"(c[2]), "+f"(c[3])
        : "r"(a[0]), "r"(a[1]), "r"(a[2]), "r"(a[3]), "r"(b0), "r"(b1));
}

// ---------------- weight transpose + fp32->half ---------------------------
// in: fp32 [K][N]  ->  out: half [N][K]
__global__ void transpose_h(const float* __restrict__ in, __half* __restrict__ out,
                            int K, int N) {
    __shared__ float tile[32][33];
    int n0 = blockIdx.x * 32, k0 = blockIdx.y * 32;
    int tx = threadIdx.x, ty = threadIdx.y;
#pragma unroll
    for (int i = 0; i < 4; i++)
        tile[ty + i * 8][tx] = in[(size_t)(k0 + ty + i * 8) * N + n0 + tx];
    __syncthreads();
#pragma unroll
    for (int i = 0; i < 4; i++)
        out[(size_t)(n0 + ty + i * 8) * K + k0 + tx] = __float2half_rn(tile[tx][ty + i * 8]);
}

__global__ void concat_bias(const float* __restrict__ bq, const float* __restrict__ bk,
                            const float* __restrict__ bv, float* __restrict__ o) {
    int i = threadIdx.x;
    const float* s = (blockIdx.x == 0) ? bq : (blockIdx.x == 1) ? bk : bv;
    o[blockIdx.x * 1024 + i] = s[i];
}

// ---------------- LayerNorm (unbiased var), fp32 + half outputs -----------
__global__ void ln_kernel(const float* __restrict__ x,
                          const float* __restrict__ alpha,
                          const float* __restrict__ beta,
                          float* __restrict__ y, __half* __restrict__ yh) {
    int row = blockIdx.x;
    int t = threadIdx.x;
    const float4* xr = (const float4*)(x + (size_t)row * DMODEL);
    float4 v = xr[t];
    float s  = v.x + v.y + v.z + v.w;
    float ss = v.x * v.x + v.y * v.y + v.z * v.z + v.w * v.w;
    __shared__ float sbuf[8], sbuf2[8];
#pragma unroll
    for (int m = 16; m; m >>= 1) {
        s  += __shfl_xor_sync(0xffffffffu, s, m);
        ss += __shfl_xor_sync(0xffffffffu, ss, m);
    }
    if ((t & 31) == 0) { sbuf[t >> 5] = s; sbuf2[t >> 5] = ss; }
    __syncthreads();
    if (t < 32) {
        s  = (t < 8) ? sbuf[t]  : 0.0f;
        ss = (t < 8) ? sbuf2[t] : 0.0f;
#pragma unroll
        for (int m = 4; m; m >>= 1) {
            s  += __shfl_xor_sync(0xffffffffu, s, m);
            ss += __shfl_xor_sync(0xffffffffu, ss, m);
        }
        if (t == 0) { sbuf[0] = s; sbuf2[0] = ss; }
    }
    __syncthreads();
    s = sbuf[0]; ss = sbuf2[0];
    float mean = s * (1.0f / DMODEL);
    float var  = (ss - (float)DMODEL * mean * mean) * (1.0f / (DMODEL - 1));
    float rstd = rsqrtf(var + 1e-6f);
    float4 a = ((const float4*)alpha)[t];
    float4 b = ((const float4*)beta)[t];
    float4 o;
    o.x = a.x * (v.x - mean) * rstd + b.x;
    o.y = a.y * (v.y - mean) * rstd + b.y;
    o.z = a.z * (v.z - mean) * rstd + b.z;
    o.w = a.w * (v.w - mean) * rstd + b.w;
    if (y) ((float4*)(y + (size_t)row * DMODEL))[t] = o;
    if (yh) {
        __half* p = yh + (size_t)row * DMODEL + t * 4;
        *(__half2*)(p)     = __floats2half2_rn(o.x, o.y);
        *(__half2*)(p + 2) = __floats2half2_rn(o.z, o.w);
    }
}

// ---------------- tensor-core GEMM  C = A[M,K] @ B[N,K]^T -----------------
// A half row-major, B half n-major (pre-transposed weights).
// block 128x128, BK=32, 8 warps (2x4), warp tile 64x32.
#define GP 40   // smem pitch in halves (80B: 16B-aligned, conflict-free)
__global__ __launch_bounds__(256) void hgemm(
    const __half* __restrict__ A, const __half* __restrict__ B,
    const float* __restrict__ bias, const float* __restrict__ res,
    float* __restrict__ Cf, __half* __restrict__ Ch,
    int M, int N, int K, int relu) {
    __shared__ __half As[128 * GP];
    __shared__ __half Bs[128 * GP];
    int t = threadIdx.x, lane = t & 31, warp = t >> 5;
    int wy = warp >> 2, wx = warp & 3;
    int bm = blockIdx.y * 128, bn = blockIdx.x * 128;

    float acc[4][4][4];
#pragma unroll
    for (int i = 0; i < 4; i++)
#pragma unroll
        for (int j = 0; j < 4; j++)
#pragma unroll
            for (int c = 0; c < 4; c++) acc[i][j][c] = 0.0f;

    const __half* Ag = A + (size_t)(bm + (t >> 1)) * K + (t & 1) * 16;
    const __half* Bg = B + (size_t)(bn + (t >> 1)) * K + (t & 1) * 16;
    __half* Asw = As + (t >> 1) * GP + (t & 1) * 16;
    __half* Bsw = Bs + (t >> 1) * GP + (t & 1) * 16;

    // per-lane ldmatrix offsets (halves)
    int arow = ((lane >> 3) & 1) * 8 + (lane & 7);
    int acol = (lane >> 4) * 8;
    int brow = (lane >> 4) * 8 + (lane & 7);
    int bcol = ((lane >> 3) & 1) * 8;
    unsigned as_u = sptr(As), bs_u = sptr(Bs);

    for (int k0 = 0; k0 < K; k0 += 32) {
        uint4 a0 = *(const uint4*)(Ag + k0);
        uint4 a1 = *(const uint4*)(Ag + k0 + 8);
        uint4 b0 = *(const uint4*)(Bg + k0);
        uint4 b1 = *(const uint4*)(Bg + k0 + 8);
        __syncthreads();
        *(uint4*)(Asw) = a0; *(uint4*)(Asw + 8) = a1;
        *(uint4*)(Bsw) = b0; *(uint4*)(Bsw + 8) = b1;
        __syncthreads();
#pragma unroll
        for (int ks = 0; ks < 2; ks++) {
            unsigned af[4][4], bf[2][4];
#pragma unroll
            for (int mi = 0; mi < 4; mi++)
                ldsm4(af[mi], as_u + 2u * ((wy * 64 + mi * 16 + arow) * GP + ks * 16 + acol));
#pragma unroll
            for (int g = 0; g < 2; g++)
                ldsm4(bf[g], bs_u + 2u * ((wx * 32 + g * 16 + brow) * GP + ks * 16 + bcol));
#pragma unroll
            for (int mi = 0; mi < 4; mi++)
#pragma unroll
                for (int ni = 0; ni < 4; ni++)
                    mma16816(acc[mi][ni], af[mi], bf[ni >> 1][(ni & 1) * 2], bf[ni >> 1][(ni & 1) * 2 + 1]);
        }
    }

#pragma unroll
    for (int mi = 0; mi < 4; mi++) {
        int r = bm + wy * 64 + mi * 16 + (lane >> 2);
#pragma unroll
        for (int ni = 0; ni < 4; ni++) {
            int c = bn + wx * 32 + ni * 8 + 2 * (lane & 3);
            float* a = acc[mi][ni];
            float2 bb = *(const float2*)(bias + c);
            float v0 = a[0] + bb.x, v1 = a[1] + bb.y;
            float v2 = a[2] + bb.x, v3 = a[3] + bb.y;
            if (res) {
                float2 r0 = *(const float2*)(res + (size_t)r * N + c);
                float2 r1 = *(const float2*)(res + (size_t)(r + 8) * N + c);
                v0 += r0.x; v1 += r0.y; v2 += r1.x; v3 += r1.y;
            }
            if (relu) {
                v0 = fmaxf(v0, 0.0f); v1 = fmaxf(v1, 0.0f);
                v2 = fmaxf(v2, 0.0f); v3 = fmaxf(v3, 0.0f);
            }
            if (Cf) {
                *(float2*)(Cf + (size_t)r * N + c)       = make_float2(v0, v1);
                *(float2*)(Cf + (size_t)(r + 8) * N + c) = make_float2(v2, v3);
            }
            if (Ch) {
                *(__half2*)(Ch + (size_t)r * N + c)       = __floats2half2_rn(v0, v1);
                *(__half2*)(Ch + (size_t)(r + 8) * N + c) = __floats2half2_rn(v2, v3);
            }
        }
    }
}

// ---------------- flash attention, tensor-core ----------------------------
// block: 8 warps, 128 q rows; K tiles of 64 tokens; q,k,v from fused g_qkv.
#define AP 72   // smem pitch (144B: aligned, conflict-free)
__global__ __launch_bounds__(256) void attn(const __half* __restrict__ qkv,
                                            __half* __restrict__ o) {
    __shared__ __half sm[128 * AP];
    int t = threadIdx.x, lane = t & 31, warp = t >> 5;
    int qt = blockIdx.x, h = blockIdx.y, b = blockIdx.z;
    size_t tq0 = (size_t)b * SEQ + qt * 128;
    const __half* Qg = qkv + tq0 * 3072 + h * 64;

    // stage Q (128 x 64 halves)
    {
        int row = t >> 1;
        const __half* src = Qg + (size_t)row * 3072 + (t & 1) * 32;
        __half* dst = sm + row * AP + (t & 1) * 32;
#pragma unroll
        for (int i = 0; i < 4; i++)
            *(uint4*)(dst + i * 8) = *(const uint4*)(src + i * 8);
    }
    __syncthreads();

    int arow = ((lane >> 3) & 1) * 8 + (lane & 7);
    int acol = (lane >> 4) * 8;
    unsigned sm_u = sptr(sm);
    unsigned qf[4][4];
#pragma unroll
    for (int ks = 0; ks < 4; ks++)
        ldsm4(qf[ks], sm_u + 2u * ((warp * 16 + arow) * AP + ks * 16 + acol));

    float m0 = -1e30f, m1 = -1e30f, l0 = 0.0f, l1 = 0.0f;
    float O[8][4];
#pragma unroll
    for (int j = 0; j < 8; j++)
#pragma unroll
        for (int c = 0; c < 4; c++) O[j][c] = 0.0f;

    __half* Ks = sm;
    __half* Vs = sm + 64 * AP;
    unsigned ks_u = sptr(Ks), vs_u = sptr(Vs);
    const __half* Kg = qkv + ((size_t)b * SEQ) * 3072 + 1024 + h * 64;
    const __half* Vg = Kg + 1024;
    int ldrow = t >> 2, ldoff = (t & 3) * 16;

    int krow = (lane >> 4) * 8 + (lane & 7);        // K frag: n=token rows
    int kcol = ((lane >> 3) & 1) * 8;
    int vrow = ((lane >> 3) & 1) * 8 + (lane & 7);  // V frag (trans): token rows
    int vcol = (lane >> 4) * 8;

    for (int kt = 0; kt < 32; kt++) {
        size_t tb = (size_t)(kt * 64 + ldrow) * 3072;
        uint4 kA = *(const uint4*)(Kg + tb + ldoff);
        uint4 kB = *(const uint4*)(Kg + tb + ldoff + 8);
        uint4 vA = *(const uint4*)(Vg + tb + ldoff);
        uint4 vB = *(const uint4*)(Vg + tb + ldoff + 8);
        __syncthreads();   // previous tile fully consumed (and Q frags on kt=0)
        *(uint4*)(Ks + ldrow * AP + ldoff)     = kA;
        *(uint4*)(Ks + ldrow * AP + ldoff + 8) = kB;
        *(uint4*)(Vs + ldrow * AP + ldoff)     = vA;
        *(uint4*)(Vs + ldrow * AP + ldoff + 8) = vB;
        __syncthreads();

        // S = Q @ K^T
        float s[8][4];
#pragma unroll
        for (int j = 0; j < 8; j++)
#pragma unroll
            for (int c = 0; c < 4; c++) s[j][c] = 0.0f;
#pragma unroll
        for (int ks = 0; ks < 4; ks++) {
            unsigned kf[4][4];
#pragma unroll
            for (int g = 0; g < 4; g++)
                ldsm4(kf[g], ks_u + 2u * ((g * 16 + krow) * AP + ks * 16 + kcol));
#pragma unroll
            for (int j = 0; j < 8; j++)
                mma16816(s[j], qf[ks], kf[j >> 1][(j & 1) * 2], kf[j >> 1][(j & 1) * 2 + 1]);
        }
        // scale + online softmax
        float mx0 = -1e30f, mx1 = -1e30f;
#pragma unroll
        for (int j = 0; j < 8; j++) {
#pragma unroll
            for (int c = 0; c < 4; c++) s[j][c] *= 0.125f;
            mx0 = fmaxf(mx0, fmaxf(s[j][0], s[j][1]));
            mx1 = fmaxf(mx1, fmaxf(s[j][2], s[j][3]));
        }
        mx0 = fmaxf(mx0, __shfl_xor_sync(0xffffffffu, mx0, 1));
        mx0 = fmaxf(mx0, __shfl_xor_sync(0xffffffffu, mx0, 2));
        mx1 = fmaxf(mx1, __shfl_xor_sync(0xffffffffu, mx1, 1));
        mx1 = fmaxf(mx1, __shfl_xor_sync(0xffffffffu, mx1, 2));
        float mn0 = fmaxf(m0, mx0), mn1 = fmaxf(m1, mx1);
        float al0 = __expf(m0 - mn0), al1 = __expf(m1 - mn1);
        m0 = mn0; m1 = mn1;
        float sum0 = 0.0f, sum1 = 0.0f;
        unsigned pa[8], pb[8];
#pragma unroll
        for (int j = 0; j < 8; j++) {
            s[j][0] = __expf(s[j][0] - mn0); s[j][1] = __expf(s[j][1] - mn0);
            s[j][2] = __expf(s[j][2] - mn1); s[j][3] = __expf(s[j][3] - mn1);
            sum0 += s[j][0] + s[j][1];
            sum1 += s[j][2] + s[j][3];
            __half2 h0 = __floats2half2_rn(s[j][0], s[j][1]);
            __half2 h1 = __floats2half2_rn(s[j][2], s[j][3]);
            pa[j] = *(unsigned*)&h0;
            pb[j] = *(unsigned*)&h1;
            O[j][0] *= al0; O[j][1] *= al0; O[j][2] *= al1; O[j][3] *= al1;
        }
        sum0 += __shfl_xor_sync(0xffffffffu, sum0, 1);
        sum0 += __shfl_xor_sync(0xffffffffu, sum0, 2);
        sum1 += __shfl_xor_sync(0xffffffffu, sum1, 1);
        sum1 += __shfl_xor_sync(0xffffffffu, sum1, 2);
        l0 = l0 * al0 + sum0;
        l1 = l1 * al1 + sum1;

        // O += P @ V
#pragma unroll
        for (int ks = 0; ks < 4; ks++) {
            unsigned vf[4][4];
#pragma unroll
            for (int g = 0; g < 4; g++)
                ldsm4t(vf[g], vs_u + 2u * ((ks * 16 + vrow) * AP + g * 16 + vcol));
            unsigned pfr[4] = {pa[2 * ks], pb[2 * ks], pa[2 * ks + 1], pb[2 * ks + 1]};
#pragma unroll
            for (int j = 0; j < 8; j++)
                mma16816(O[j], pfr, vf[j >> 1][(j & 1) * 2], vf[j >> 1][(j & 1) * 2 + 1]);
        }
    }

    float i0 = 1.0f / l0, i1 = 1.0f / l1;
    __half* ob = o + (tq0 + warp * 16 + (lane >> 2)) * 1024 + h * 64 + 2 * (lane & 3);
#pragma unroll
    for (int j = 0; j < 8; j++) {
        *(__half2*)(ob + j * 8)             = __floats2half2_rn(O[j][0] * i0, O[j][1] * i0);
        *(__half2*)(ob + 8 * 1024 + j * 8)  = __floats2half2_rn(O[j][2] * i1, O[j][3] * i1);
    }
}

// ---------------------------------------------------------------------------
extern "C" void kernel_launch(void* const* d_in, const int* in_sizes, int n_in,
                              void* d_out, int out_size) {
    const float* x      = (const float*)d_in[0];
    const float* Wq     = (const float*)d_in[1];
    const float* bq     = (const float*)d_in[2];
    const float* Wk     = (const float*)d_in[3];
    const float* bk     = (const float*)d_in[4];
    const float* Wv     = (const float*)d_in[5];
    const float* bv     = (const float*)d_in[6];
    const float* Wo     = (const float*)d_in[7];
    const float* bo     = (const float*)d_in[8];
    const float* alpha1 = (const float*)d_in[9];
    const float* beta1  = (const float*)d_in[10];
    const float* alpha2 = (const float*)d_in[11];
    const float* beta2  = (const float*)d_in[12];
    const float* W1     = (const float*)d_in[13];
    const float* b1     = (const float*)d_in[14];
    const float* W2     = (const float*)d_in[15];
    const float* b2     = (const float*)d_in[16];
    float* out = (float*)d_out;

    float *p_xn, *p_x1, *p_bqkv;
    __half *p_xn_h, *p_qkv, *p_attn_h, *p_h_h, *p_hf;
    __half *p_Wqkv, *p_WoT, *p_W1T, *p_W2T;
    cudaGetSymbolAddress((void**)&p_xn,     g_xn);
    cudaGetSymbolAddress((void**)&p_xn_h,   g_xn_h);
    cudaGetSymbolAddress((void**)&p_qkv,    g_qkv);
    cudaGetSymbolAddress((void**)&p_attn_h, g_attn_h);
    cudaGetSymbolAddress((void**)&p_x1,     g_x1);
    cudaGetSymbolAddress((void**)&p_h_h,    g_h_h);
    cudaGetSymbolAddress((void**)&p_hf,     g_hf);
    cudaGetSymbolAddress((void**)&p_Wqkv,   g_Wqkv);
    cudaGetSymbolAddress((void**)&p_WoT,    g_WoT);
    cudaGetSymbolAddress((void**)&p_W1T,    g_W1T);
    cudaGetSymbolAddress((void**)&p_W2T,    g_W2T);
    cudaGetSymbolAddress((void**)&p_bqkv,   g_bqkv);

    dim3 tb(32, 8);
    // weight prep: [K][N] fp32 -> [N][K] half
    transpose_h<<<dim3(32, 32), tb>>>(Wq, p_Wqkv,               1024, 1024);
    transpose_h<<<dim3(32, 32), tb>>>(Wk, p_Wqkv + 1024 * 1024, 1024, 1024);
    transpose_h<<<dim3(32, 32), tb>>>(Wv, p_Wqkv + 2048 * 1024, 1024, 1024);
    transpose_h<<<dim3(32, 32), tb>>>(Wo, p_WoT, 1024, 1024);
    transpose_h<<<dim3(16, 32), tb>>>(W1, p_W1T, 1024, 512);
    transpose_h<<<dim3(32, 16), tb>>>(W2, p_W2T, 512, 1024);
    concat_bias<<<3, 1024>>>(bq, bk, bv, p_bqkv);

    // 1. LN1 -> xn (fp32 residual) + xn_h (GEMM input)
    ln_kernel<<<NTOK, 256>>>(x, alpha1, beta1, p_xn, p_xn_h);
    // 2. fused QKV projection (half out)
    hgemm<<<dim3(24, 32), 256>>>(p_xn_h, p_Wqkv, p_bqkv, nullptr,
                                 nullptr, p_qkv, NTOK, 3072, 1024, 0);
    // 3. attention
    attn<<<dim3(SEQ / 128, NH, 2), 256>>>(p_qkv, p_attn_h);
    // 4. O projection + residual(xn) -> x1 fp32
    hgemm<<<dim3(8, 32), 256>>>(p_attn_h, p_WoT, bo, p_xn,
                                p_x1, nullptr, NTOK, 1024, 1024, 0);
    // 5. LN2 -> h_h
    ln_kernel<<<NTOK, 256>>>(p_x1, alpha2, beta2, nullptr, p_h_h);
    // 6. FF1 + relu (half out)
    hgemm<<<dim3(4, 32), 256>>>(p_h_h, p_W1T, b1, nullptr,
                                nullptr, p_hf, NTOK, 512, 1024, 1);
    // 7. FF2 + residual(x1) -> out fp32
    hgemm<<<dim3(8, 32), 256>>>(p_hf, p_W2T, b2, p_x1,
                                out, nullptr, NTOK, 1024, 512, 0);
}

// round 5
// speedup vs baseline: 5.9235x; 1.1050x over previous
#include <cuda_runtime.h>
#include <cuda_fp16.h>
#include <math.h>

#define NTOK 4096
#define DMODEL 1024
#define DFF 512
#define NH 16
#define DH 64
#define SEQ 2048

// ---------------- scratch (device globals: alloc-free, capture-safe) -------
__device__ float  g_xn[NTOK * DMODEL];
__device__ __half g_xn_h[NTOK * DMODEL];
__device__ __half g_qkv[NTOK * 3 * DMODEL];
__device__ __half g_attn_h[NTOK * DMODEL];
__device__ float  g_x1[NTOK * DMODEL];
__device__ __half g_h_h[NTOK * DMODEL];
__device__ __half g_hf[NTOK * DFF];
__device__ __half g_Wqkv[3 * DMODEL * DMODEL];
__device__ __half g_WoT[DMODEL * DMODEL];
__device__ __half g_W1T[DFF * DMODEL];
__device__ __half g_W2T[DMODEL * DFF];
__device__ float  g_bqkv[3 * DMODEL];

// ---------------- PTX helpers ---------------------------------------------
__device__ __forceinline__ unsigned sptr(const void* p) {
    return (unsigned)__cvta_generic_to_shared(p);
}
__device__ __forceinline__ void ldsm4(unsigned* r, unsigned addr) {
    asm volatile("ldmatrix.sync.aligned.m8n8.x4.shared.b16 {%0,%1,%2,%3}, [%4];"
        : "=r"(r[0]), "=r"(r[1]), "=r"(r[2]), "=r"(r[3]) : "r"(addr));
}
__device__ __forceinline__ void ldsm4t(unsigned* r, unsigned addr) {
    asm volatile("ldmatrix.sync.aligned.m8n8.x4.trans.shared.b16 {%0,%1,%2,%3}, [%4];"
        : "=r"(r[0]), "=r"(r[1]), "=r"(r[2]), "=r"(r[3]) : "r"(addr));
}
__device__ __forceinline__ void mma16816(float* c, const unsigned* a, unsigned b0, unsigned b1) {
    asm volatile("mma.sync.aligned.m16n8k16.row.col.f32.f16.f16.f32 "
        "{%0,%1,%2,%3},{%4,%5,%6,%7},{%8,%9},{%0,%1,%2,%3};"
        : "+f"(c[0]), "+f"(c[1]), "+f"(c[2]), "+f"(c[3])
        : "r"(a[0]), "r"(a[1]), "r"(a[2]), "r"(a[3]), "r"(b0), "r"(b1));
}
__device__ __forceinline__ void cpa16(unsigned dst, const void* src) {
    asm volatile("cp.async.cg.shared.global [%0], [%1], 16;" :: "r"(dst), "l"(src));
}
__device__ __forceinline__ void cp_commit() { asm volatile("cp.async.commit_group;"); }
__device__ __forceinline__ void cp_wait0()  { asm volatile("cp.async.wait_group 0;"); }

// ---------------- fused weight prep: transpose + fp32->half + bias --------
// tiles: [0,3072) Wq/Wk/Wv  [3072,4096) Wo  [4096,4608) W1  [4608,5120) W2
// [5120,5123) bias concat
__global__ void prep_weights(const float* __restrict__ Wq, const float* __restrict__ Wk,
                             const float* __restrict__ Wv, const float* __restrict__ Wo,
                             const float* __restrict__ W1, const float* __restrict__ W2,
                             const float* __restrict__ bq, const float* __restrict__ bk,
                             const float* __restrict__ bv,
                             __half* __restrict__ Wqkv, __half* __restrict__ WoT,
                             __half* __restrict__ W1T, __half* __restrict__ W2T,
                             float* __restrict__ bqkv) {
    int id = blockIdx.x;
    int tx = threadIdx.x, ty = threadIdx.y;
    if (id >= 5120) {
        int w = id - 5120;
        const float* s = (w == 0) ? bq : (w == 1) ? bk : bv;
        int i = ty * 32 + tx;
#pragma unroll
        for (int j = 0; j < 4; j++) bqkv[w * 1024 + i + j * 256] = s[i + j * 256];
        return;
    }
    const float* src; __half* dst; int K, N, tile;
    if (id < 3072) {
        int w = id >> 10; tile = id & 1023;
        src = (w == 0) ? Wq : (w == 1) ? Wk : Wv;
        dst = Wqkv + (size_t)w * 1024 * 1024; K = 1024; N = 1024;
    } else if (id < 4096) { tile = id - 3072; src = Wo; dst = WoT; K = 1024; N = 1024; }
    else if (id < 4608)   { tile = id - 4096; src = W1; dst = W1T; K = 1024; N = 512; }
    else                  { tile = id - 4608; src = W2; dst = W2T; K = 512;  N = 1024; }
    int ntx = N >> 5;
    int k0 = (tile / ntx) * 32, n0 = (tile % ntx) * 32;
    __shared__ float t2[32][33];
#pragma unroll
    for (int i = 0; i < 4; i++)
        t2[ty + i * 8][tx] = src[(size_t)(k0 + ty + i * 8) * N + n0 + tx];
    __syncthreads();
#pragma unroll
    for (int i = 0; i < 4; i++)
        dst[(size_t)(n0 + ty + i * 8) * K + k0 + tx] = __float2half_rn(t2[tx][ty + i * 8]);
}

// ---------------- LayerNorm (unbiased var), fp32 + half outputs -----------
__global__ void ln_kernel(const float* __restrict__ x,
                          const float* __restrict__ alpha,
                          const float* __restrict__ beta,
                          float* __restrict__ y, __half* __restrict__ yh) {
    int row = blockIdx.x;
    int t = threadIdx.x;
    const float4* xr = (const float4*)(x + (size_t)row * DMODEL);
    float4 v = xr[t];
    float s  = v.x + v.y + v.z + v.w;
    float ss = v.x * v.x + v.y * v.y + v.z * v.z + v.w * v.w;
    __shared__ float sbuf[8], sbuf2[8];
#pragma unroll
    for (int m = 16; m; m >>= 1) {
        s  += __shfl_xor_sync(0xffffffffu, s, m);
        ss += __shfl_xor_sync(0xffffffffu, ss, m);
    }
    if ((t & 31) == 0) { sbuf[t >> 5] = s; sbuf2[t >> 5] = ss; }
    __syncthreads();
    if (t < 32) {
        s  = (t < 8) ? sbuf[t]  : 0.0f;
        ss = (t < 8) ? sbuf2[t] : 0.0f;
#pragma unroll
        for (int m = 4; m; m >>= 1) {
            s  += __shfl_xor_sync(0xffffffffu, s, m);
            ss += __shfl_xor_sync(0xffffffffu, ss, m);
        }
        if (t == 0) { sbuf[0] = s; sbuf2[0] = ss; }
    }
    __syncthreads();
    s = sbuf[0]; ss = sbuf2[0];
    float mean = s * (1.0f / DMODEL);
    float var  = (ss - (float)DMODEL * mean * mean) * (1.0f / (DMODEL - 1));
    float rstd = rsqrtf(var + 1e-6f);
    float4 a = ((const float4*)alpha)[t];
    float4 b = ((const float4*)beta)[t];
    float4 o;
    o.x = a.x * (v.x - mean) * rstd + b.x;
    o.y = a.y * (v.y - mean) * rstd + b.y;
    o.z = a.z * (v.z - mean) * rstd + b.z;
    o.w = a.w * (v.w - mean) * rstd + b.w;
    if (y) ((float4*)(y + (size_t)row * DMODEL))[t] = o;
    if (yh) {
        __half* p = yh + (size_t)row * DMODEL + t * 4;
        *(__half2*)(p)     = __floats2half2_rn(o.x, o.y);
        *(__half2*)(p + 2) = __floats2half2_rn(o.z, o.w);
    }
}

// ---------------- tensor-core GEMM, cp.async 2-stage pipeline -------------
// C = A[M,K] @ B[N,K]^T.  block 128x128, BK=32, 8 warps (2x4), warp 64x32.
#define GP 40
__global__ __launch_bounds__(256) void hgemm(
    const __half* __restrict__ A, const __half* __restrict__ B,
    const float* __restrict__ bias, const float* __restrict__ res,
    float* __restrict__ Cf, __half* __restrict__ Ch,
    int M, int N, int K, int relu) {
    __shared__ __half As[2][128 * GP];
    __shared__ __half Bs[2][128 * GP];
    int t = threadIdx.x, lane = t & 31, warp = t >> 5;
    int wy = warp >> 2, wx = warp & 3;
    int bm = blockIdx.y * 128, bn = blockIdx.x * 128;

    float acc[4][4][4];
#pragma unroll
    for (int i = 0; i < 4; i++)
#pragma unroll
        for (int j = 0; j < 4; j++)
#pragma unroll
            for (int c = 0; c < 4; c++) acc[i][j][c] = 0.0f;

    const __half* Ag = A + (size_t)(bm + (t >> 1)) * K + (t & 1) * 16;
    const __half* Bg = B + (size_t)(bn + (t >> 1)) * K + (t & 1) * 16;
    unsigned ldoff = ((t >> 1) * GP + (t & 1) * 16) * 2;   // bytes
    unsigned asb[2] = {sptr(As[0]), sptr(As[1])};
    unsigned bsb[2] = {sptr(Bs[0]), sptr(Bs[1])};

    int arow = ((lane >> 3) & 1) * 8 + (lane & 7);
    int acol = (lane >> 4) * 8;
    int brow = (lane >> 4) * 8 + (lane & 7);
    int bcol = ((lane >> 3) & 1) * 8;

    // prologue: stage 0
    {
        cpa16(asb[0] + ldoff, Ag);      cpa16(asb[0] + ldoff + 16, Ag + 8);
        cpa16(bsb[0] + ldoff, Bg);      cpa16(bsb[0] + ldoff + 16, Bg + 8);
        cp_commit();
    }
    int nIter = K >> 5;
    for (int it = 0; it < nIter; it++) {
        cp_wait0();
        __syncthreads();
        if (it + 1 < nIter) {
            int st = (it + 1) & 1, k0 = (it + 1) << 5;
            cpa16(asb[st] + ldoff, Ag + k0);      cpa16(asb[st] + ldoff + 16, Ag + k0 + 8);
            cpa16(bsb[st] + ldoff, Bg + k0);      cpa16(bsb[st] + ldoff + 16, Bg + k0 + 8);
            cp_commit();
        }
        unsigned as_u = asb[it & 1], bs_u = bsb[it & 1];
#pragma unroll
        for (int ks = 0; ks < 2; ks++) {
            unsigned af[4][4], bf[2][4];
#pragma unroll
            for (int mi = 0; mi < 4; mi++)
                ldsm4(af[mi], as_u + 2u * ((wy * 64 + mi * 16 + arow) * GP + ks * 16 + acol));
#pragma unroll
            for (int g = 0; g < 2; g++)
                ldsm4(bf[g], bs_u + 2u * ((wx * 32 + g * 16 + brow) * GP + ks * 16 + bcol));
#pragma unroll
            for (int mi = 0; mi < 4; mi++)
#pragma unroll
                for (int ni = 0; ni < 4; ni++)
                    mma16816(acc[mi][ni], af[mi], bf[ni >> 1][(ni & 1) * 2], bf[ni >> 1][(ni & 1) * 2 + 1]);
        }
    }

#pragma unroll
    for (int mi = 0; mi < 4; mi++) {
        int r = bm + wy * 64 + mi * 16 + (lane >> 2);
#pragma unroll
        for (int ni = 0; ni < 4; ni++) {
            int c = bn + wx * 32 + ni * 8 + 2 * (lane & 3);
            float* a = acc[mi][ni];
            float2 bb = *(const float2*)(bias + c);
            float v0 = a[0] + bb.x, v1 = a[1] + bb.y;
            float v2 = a[2] + bb.x, v3 = a[3] + bb.y;
            if (res) {
                float2 r0 = *(const float2*)(res + (size_t)r * N + c);
                float2 r1 = *(const float2*)(res + (size_t)(r + 8) * N + c);
                v0 += r0.x; v1 += r0.y; v2 += r1.x; v3 += r1.y;
            }
            if (relu) {
                v0 = fmaxf(v0, 0.0f); v1 = fmaxf(v1, 0.0f);
                v2 = fmaxf(v2, 0.0f); v3 = fmaxf(v3, 0.0f);
            }
            if (Cf) {
                *(float2*)(Cf + (size_t)r * N + c)       = make_float2(v0, v1);
                *(float2*)(Cf + (size_t)(r + 8) * N + c) = make_float2(v2, v3);
            }
            if (Ch) {
                *(__half2*)(Ch + (size_t)r * N + c)       = __floats2half2_rn(v0, v1);
                *(__half2*)(Ch + (size_t)(r + 8) * N + c) = __floats2half2_rn(v2, v3);
            }
        }
    }
}

// ---------------- flash attention, cp.async double-buffered ---------------
// 8 warps, 128 q rows/block; 64-token K tiles; Q smem region recycled as stage 1.
#define AP 72
__global__ __launch_bounds__(256) void attn(const __half* __restrict__ qkv,
                                            __half* __restrict__ o) {
    __shared__ __half smA[128 * AP];   // Q staging, then K/V stage 1
    __shared__ __half smB[128 * AP];   // K/V stage 0
    int t = threadIdx.x, lane = t & 31, warp = t >> 5;
    int qt = blockIdx.x, h = blockIdx.y, b = blockIdx.z;
    size_t tq0 = (size_t)b * SEQ + qt * 128;
    const __half* Qg = qkv + tq0 * 3072 + h * 64;
    const __half* Kg = qkv + ((size_t)b * SEQ) * 3072 + 1024 + h * 64;
    const __half* Vg = Kg + 1024;

    __half* Kst[2] = {smB, smA};
    __half* Vst[2] = {smB + 64 * AP, smA + 64 * AP};
    unsigned ksu[2] = {sptr(Kst[0]), sptr(Kst[1])};
    unsigned vsu[2] = {sptr(Vst[0]), sptr(Vst[1])};

    int ldrow = t >> 2, ldo = (t & 3) * 16;
    unsigned kvoff = (ldrow * AP + ldo) * 2;

    // prologue: issue K/V tile 0 into stage 0 (region B) first — overlaps Q staging
    {
        size_t tb = (size_t)ldrow * 3072;
        cpa16(ksu[0] + kvoff, Kg + tb + ldo);      cpa16(ksu[0] + kvoff + 16, Kg + tb + ldo + 8);
        cpa16(vsu[0] + kvoff, Vg + tb + ldo);      cpa16(vsu[0] + kvoff + 16, Vg + tb + ldo + 8);
        cp_commit();
    }

    // stage Q (128 x 64 halves) into region A
    {
        int row = t >> 1;
        const __half* src = Qg + (size_t)row * 3072 + (t & 1) * 32;
        __half* dst = smA + row * AP + (t & 1) * 32;
#pragma unroll
        for (int i = 0; i < 4; i++)
            *(uint4*)(dst + i * 8) = *(const uint4*)(src + i * 8);
    }
    __syncthreads();

    int arow = ((lane >> 3) & 1) * 8 + (lane & 7);
    int acol = (lane >> 4) * 8;
    unsigned smA_u = sptr(smA);
    unsigned qf[4][4];
#pragma unroll
    for (int ks = 0; ks < 4; ks++)
        ldsm4(qf[ks], smA_u + 2u * ((warp * 16 + arow) * AP + ks * 16 + acol));

    float m0 = -1e30f, m1 = -1e30f, l0 = 0.0f, l1 = 0.0f;
    float O[8][4];
#pragma unroll
    for (int j = 0; j < 8; j++)
#pragma unroll
        for (int c = 0; c < 4; c++) O[j][c] = 0.0f;

    int krow = (lane >> 4) * 8 + (lane & 7);
    int kcol = ((lane >> 3) & 1) * 8;
    int vrow = ((lane >> 3) & 1) * 8 + (lane & 7);
    int vcol = (lane >> 4) * 8;

    for (int kt = 0; kt < 32; kt++) {
        cp_wait0();
        __syncthreads();   // tile kt resident; also: all warps done with prior stage + Q frags
        if (kt + 1 < 32) {
            int st = (kt + 1) & 1;
            size_t tb = (size_t)((kt + 1) * 64 + ldrow) * 3072;
            cpa16(ksu[st] + kvoff, Kg + tb + ldo);      cpa16(ksu[st] + kvoff + 16, Kg + tb + ldo + 8);
            cpa16(vsu[st] + kvoff, Vg + tb + ldo);      cpa16(vsu[st] + kvoff + 16, Vg + tb + ldo + 8);
            cp_commit();
        }
        unsigned ks_u = ksu[kt & 1], vs_u = vsu[kt & 1];

        // S = Q @ K^T
        float s[8][4];
#pragma unroll
        for (int j = 0; j < 8; j++)
#pragma unroll
            for (int c = 0; c < 4; c++) s[j][c] = 0.0f;
#pragma unroll
        for (int ks = 0; ks < 4; ks++) {
            unsigned kf[4][4];
#pragma unroll
            for (int g = 0; g < 4; g++)
                ldsm4(kf[g], ks_u + 2u * ((g * 16 + krow) * AP + ks * 16 + kcol));
#pragma unroll
            for (int j = 0; j < 8; j++)
                mma16816(s[j], qf[ks], kf[j >> 1][(j & 1) * 2], kf[j >> 1][(j & 1) * 2 + 1]);
        }
        // scale + online softmax
        float mx0 = -1e30f, mx1 = -1e30f;
#pragma unroll
        for (int j = 0; j < 8; j++) {
#pragma unroll
            for (int c = 0; c < 4; c++) s[j][c] *= 0.125f;
            mx0 = fmaxf(mx0, fmaxf(s[j][0], s[j][1]));
            mx1 = fmaxf(mx1, fmaxf(s[j][2], s[j][3]));
        }
        mx0 = fmaxf(mx0, __shfl_xor_sync(0xffffffffu, mx0, 1));
        mx0 = fmaxf(mx0, __shfl_xor_sync(0xffffffffu, mx0, 2));
        mx1 = fmaxf(mx1, __shfl_xor_sync(0xffffffffu, mx1, 1));
        mx1 = fmaxf(mx1, __shfl_xor_sync(0xffffffffu, mx1, 2));
        float mn0 = fmaxf(m0, mx0), mn1 = fmaxf(m1, mx1);
        float al0 = __expf(m0 - mn0), al1 = __expf(m1 - mn1);
        m0 = mn0; m1 = mn1;
        float sum0 = 0.0f, sum1 = 0.0f;
        unsigned pa[8], pb[8];
#pragma unroll
        for (int j = 0; j < 8; j++) {
            s[j][0] = __expf(s[j][0] - mn0); s[j][1] = __expf(s[j][1] - mn0);
            s[j][2] = __expf(s[j][2] - mn1); s[j][3] = __expf(s[j][3] - mn1);
            sum0 += s[j][0] + s[j][1];
            sum1 += s[j][2] + s[j][3];
            __half2 h0 = __floats2half2_rn(s[j][0], s[j][1]);
            __half2 h1 = __floats2half2_rn(s[j][2], s[j][3]);
            pa[j] = *(unsigned*)&h0;
            pb[j] = *(unsigned*)&h1;
            O[j][0] *= al0; O[j][1] *= al0; O[j][2] *= al1; O[j][3] *= al1;
        }
        sum0 += __shfl_xor_sync(0xffffffffu, sum0, 1);
        sum0 += __shfl_xor_sync(0xffffffffu, sum0, 2);
        sum1 += __shfl_xor_sync(0xffffffffu, sum1, 1);
        sum1 += __shfl_xor_sync(0xffffffffu, sum1, 2);
        l0 = l0 * al0 + sum0;
        l1 = l1 * al1 + sum1;

        // O += P @ V
#pragma unroll
        for (int ks = 0; ks < 4; ks++) {
            unsigned vf[4][4];
#pragma unroll
            for (int g = 0; g < 4; g++)
                ldsm4t(vf[g], vs_u + 2u * ((ks * 16 + vrow) * AP + g * 16 + vcol));
            unsigned pfr[4] = {pa[2 * ks], pb[2 * ks], pa[2 * ks + 1], pb[2 * ks + 1]};
#pragma unroll
            for (int j = 0; j < 8; j++)
                mma16816(O[j], pfr, vf[j >> 1][(j & 1) * 2], vf[j >> 1][(j & 1) * 2 + 1]);
        }
    }

    float i0 = 1.0f / l0, i1 = 1.0f / l1;
    __half* ob = o + (tq0 + warp * 16 + (lane >> 2)) * 1024 + h * 64 + 2 * (lane & 3);
#pragma unroll
    for (int j = 0; j < 8; j++) {
        *(__half2*)(ob + j * 8)            = __floats2half2_rn(O[j][0] * i0, O[j][1] * i0);
        *(__half2*)(ob + 8 * 1024 + j * 8) = __floats2half2_rn(O[j][2] * i1, O[j][3] * i1);
    }
}

// ---------------------------------------------------------------------------
extern "C" void kernel_launch(void* const* d_in, const int* in_sizes, int n_in,
                              void* d_out, int out_size) {
    const float* x      = (const float*)d_in[0];
    const float* Wq     = (const float*)d_in[1];
    const float* bq     = (const float*)d_in[2];
    const float* Wk     = (const float*)d_in[3];
    const float* bk     = (const float*)d_in[4];
    const float* Wv     = (const float*)d_in[5];
    const float* bv     = (const float*)d_in[6];
    const float* Wo     = (const float*)d_in[7];
    const float* bo     = (const float*)d_in[8];
    const float* alpha1 = (const float*)d_in[9];
    const float* beta1  = (const float*)d_in[10];
    const float* alpha2 = (const float*)d_in[11];
    const float* beta2  = (const float*)d_in[12];
    const float* W1     = (const float*)d_in[13];
    const float* b1     = (const float*)d_in[14];
    const float* W2     = (const float*)d_in[15];
    const float* b2     = (const float*)d_in[16];
    float* out = (float*)d_out;

    float *p_xn, *p_x1, *p_bqkv;
    __half *p_xn_h, *p_qkv, *p_attn_h, *p_h_h, *p_hf;
    __half *p_Wqkv, *p_WoT, *p_W1T, *p_W2T;
    cudaGetSymbolAddress((void**)&p_xn,     g_xn);
    cudaGetSymbolAddress((void**)&p_xn_h,   g_xn_h);
    cudaGetSymbolAddress((void**)&p_qkv,    g_qkv);
    cudaGetSymbolAddress((void**)&p_attn_h, g_attn_h);
    cudaGetSymbolAddress((void**)&p_x1,     g_x1);
    cudaGetSymbolAddress((void**)&p_h_h,    g_h_h);
    cudaGetSymbolAddress((void**)&p_hf,     g_hf);
    cudaGetSymbolAddress((void**)&p_Wqkv,   g_Wqkv);
    cudaGetSymbolAddress((void**)&p_WoT,    g_WoT);
    cudaGetSymbolAddress((void**)&p_W1T,    g_W1T);
    cudaGetSymbolAddress((void**)&p_W2T,    g_W2T);
    cudaGetSymbolAddress((void**)&p_bqkv,   g_bqkv);

    // 0. fused weight prep (runs concurrently-ish with LN1 on same stream order)
    prep_weights<<<5123, dim3(32, 8)>>>(Wq, Wk, Wv, Wo, W1, W2, bq, bk, bv,
                                        p_Wqkv, p_WoT, p_W1T, p_W2T, p_bqkv);
    // 1. LN1 -> xn (fp32 residual) + xn_h
    ln_kernel<<<NTOK, 256>>>(x, alpha1, beta1, p_xn, p_xn_h);
    // 2. fused QKV projection
    hgemm<<<dim3(24, 32), 256>>>(p_xn_h, p_Wqkv, p_bqkv, nullptr,
                                 nullptr, p_qkv, NTOK, 3072, 1024, 0);
    // 3. attention
    attn<<<dim3(SEQ / 128, NH, 2), 256>>>(p_qkv, p_attn_h);
    // 4. O projection + residual(xn) -> x1
    hgemm<<<dim3(8, 32), 256>>>(p_attn_h, p_WoT, bo, p_xn,
                                p_x1, nullptr, NTOK, 1024, 1024, 0);
    // 5. LN2 -> h_h
    ln_kernel<<<NTOK, 256>>>(p_x1, alpha2, beta2, nullptr, p_h_h);
    // 6. FF1 + relu
    hgemm<<<dim3(4, 32), 256>>>(p_h_h, p_W1T, b1, nullptr,
                                nullptr, p_hf, NTOK, 512, 1024, 1);
    // 7. FF2 + residual(x1) -> out
    hgemm<<<dim3(8, 32), 256>>>(p_hf, p_W2T, b2, p_x1,
                                out, nullptr, NTOK, 1024, 512, 0);
}